// round 10
// baseline (speedup 1.0000x reference)
#include <cuda_runtime.h>
#include <cuda_bf16.h>

#define TLEN   512
#define FDIM   1024
#define NW     16            // warps per block = time chunks
#define CHUNK  (TLEN / NW)   // 32 timesteps per warp
#define SSM    16            // steps staged in smem
#define SRG    16            // steps staged in registers
#define NTILES 1024          // B(32) * f-tiles(32)
#define NBLOCKS 444          // 3 blocks/SM * 148 SMs -> single wave

__device__ unsigned g_work = 0;   // next dynamic tile - NBLOCKS
__device__ unsigned g_done = 0;   // finished-block count (last one resets)

__device__ __forceinline__ float fast_sqrt(float a) {
    float r; asm("sqrt.approx.f32 %0, %1;" : "=f"(r) : "f"(a)); return r;
}
__device__ __forceinline__ float fast_tanh(float a) {
    float r; asm("tanh.approx.f32 %0, %1;" : "=f"(r) : "f"(a)); return r;
}

__global__ __launch_bounds__(NW * 32, 3)
void dyn_dense_kernel(const float* __restrict__ x, const float* __restrict__ ws,
                      const float* __restrict__ qs, const float* __restrict__ bias,
                      float* __restrict__ out)
{
    __shared__ float s_invc[TLEN];                 // 2 KB
    __shared__ float sm_x[NW][SSM][32];            // 32 KB staged chunk halves
    __shared__ float sm_s[NW][32];                 // partials
    __shared__ float sm_m[NW][32];
    __shared__ float sm_q[NW][32];
    __shared__ unsigned sh_tile;

    const int tid  = threadIdx.x;
    const int warp = tid >> 5;
    const int lane = tid & 31;

    s_invc[tid] = 1.0f / (float)(tid + 1);         // 512 threads, one each

    unsigned tile = blockIdx.x;                    // static first tile

    while (true) {
        // tile -> (batch, f-tile)
        const int fblk = tile & (FDIM / 32 - 1);
        const int b    = tile >> 5;
        const int f    = fblk * 32 + lane;

        const size_t colbase = (size_t)b * TLEN * FDIM + (size_t)(warp * CHUNK) * FDIM + f;
        const float* p = x + colbase;

        // ---- Phase 1: load chunk ONCE; stage half to smem, half to regs ----
        // Max identity 0.0f matches the Keras zero-init of the max state.
        float ps = 0.0f, pm = 0.0f, pq = 0.0f;
        {
            float xv[SSM];
            #pragma unroll
            for (int u = 0; u < SSM; u++)
                xv[u] = __ldg(p + u * FDIM);       // 16 LDGs in flight
            #pragma unroll
            for (int u = 0; u < SSM; u++) {
                sm_x[warp][u][lane] = xv[u];       // conflict-free row store
                ps += xv[u];
                pq  = fmaf(xv[u], xv[u], pq);
                pm  = fmaxf(pm, xv[u]);
            }
        }   // xv dead -> peak regs stays low
        float xr[SRG];
        #pragma unroll
        for (int u = 0; u < SRG; u++)
            xr[u] = __ldg(p + (SSM + u) * FDIM);
        #pragma unroll
        for (int u = 0; u < SRG; u++) {
            ps += xr[u];
            pq  = fmaf(xr[u], xr[u], pq);
            pm  = fmaxf(pm, xr[u]);
        }
        sm_s[warp][lane] = ps;
        sm_m[warp][lane] = pm;
        sm_q[warp][lane] = pq;
        __syncthreads();

        // ---- Phase 2: exclusive prefix over earlier chunks ----
        float s = 0.0f, m = 0.0f, ss = 0.0f;
        #pragma unroll
        for (int w = 0; w < NW - 1; w++) {
            if (w < warp) {
                s  += sm_s[w][lane];
                m   = fmaxf(m, sm_m[w][lane]);
                ss += sm_q[w][lane];
            }
        }

        // per-aggregation weights: AGGS = (sum, max, mean, var, std)
        const float w0 = __ldg(ws + 0 * FDIM + f);
        const float w1 = __ldg(ws + 1 * FDIM + f);
        const float w2 = __ldg(ws + 2 * FDIM + f);
        const float w3 = __ldg(ws + 3 * FDIM + f);
        const float w4 = __ldg(ws + 4 * FDIM + f);
        const float q0 = __ldg(qs + 0 * FDIM + f);
        const float q1 = __ldg(qs + 1 * FDIM + f);
        // fold exact eps-correction into bias: z-chain uses w3*(var+eps)
        const float bz = fmaf(-w3, 1e-4f, __ldg(bias + f));

        float c = (float)(warp * CHUNK);
        float* o = out + colbase;
        const float* icp = &s_invc[warp * CHUNK];

        auto step = [&](float xt, int t) {
            c += 1.0f;
            const float ic = icp[t];               // broadcast LDS

            s  += xt;
            ss  = fmaf(xt, xt, ss);
            m   = fmaxf(m, xt);

            const float mean = s * ic;
            const float veps = fmaf(-mean, mean, fmaf(ss, ic, 1e-4f)); // var + eps
            const float stdv = fast_sqrt(veps);

            float z = fmaf(q1, c, q0);             // count polynomial
            z = fmaf(z, c, bz);                    // bz holds eps fix
            z = fmaf(w0, s,    z);
            z = fmaf(w1, m,    z);
            z = fmaf(w2, mean, z);
            z = fmaf(w3, veps, z);
            z = fmaf(w4, stdv, z);

            o[t * FDIM] = fast_tanh(z);
        };

        // steps 0..15 from smem stage, 16..31 from regs; no global reads here
        #pragma unroll
        for (int u = 0; u < SSM; u++)
            step(sm_x[warp][u][lane], u);
        #pragma unroll
        for (int u = 0; u < SRG; u++)
            step(xr[u], SSM + u);

        // ---- grab next tile (work stealing) ----
        if (tid == 0)
            sh_tile = NBLOCKS + atomicAdd(&g_work, 1u);
        __syncthreads();   // also separates this tile's sm_x reads from next tile's writes
        tile = sh_tile;
        if (tile >= NTILES) break;
    }

    // last block to finish resets the counters for the next (graph-replayed) launch
    if (tid == 0) {
        unsigned d = atomicAdd(&g_done, 1u);
        if (d == NBLOCKS - 1) {
            g_work = 0;
            g_done = 0;
            __threadfence();
        }
    }
}

extern "C" void kernel_launch(void* const* d_in, const int* in_sizes, int n_in,
                              void* d_out, int out_size)
{
    const float* x    = (const float*)d_in[0];
    const float* ws   = (const float*)d_in[1];
    const float* qs   = (const float*)d_in[2];
    const float* bias = (const float*)d_in[3];
    float* out = (float*)d_out;

    dyn_dense_kernel<<<NBLOCKS, NW * 32>>>(x, ws, qs, bias, out);
}

// round 11
// speedup vs baseline: 1.3074x; 1.3074x over previous
#include <cuda_runtime.h>
#include <cuda_bf16.h>
#include <cstdint>

#define TLEN  512
#define FDIM  1024
#define NW    16            // warps per block = time chunks
#define CHUNK (TLEN / NW)   // 32 timesteps per warp
#define U1    16            // phase-1 float2 load batch
#define U2    4             // phase-2 float2 batch, double-buffered
#define F2    (FDIM / 2)    // row stride in float2

typedef unsigned long long ull;

__device__ __forceinline__ float fast_sqrt(float a) {
    float r; asm("sqrt.approx.f32 %0, %1;" : "=f"(r) : "f"(a)); return r;
}
__device__ __forceinline__ float fast_tanh(float a) {
    float r; asm("tanh.approx.f32 %0, %1;" : "=f"(r) : "f"(a)); return r;
}
// ---- packed f32x2 (sm_100+) ----
__device__ __forceinline__ ull pack2(float lo, float hi) {
    ull r; asm("mov.b64 %0, {%1, %2};" : "=l"(r) : "f"(lo), "f"(hi)); return r;
}
__device__ __forceinline__ void unpack2(ull v, float& lo, float& hi) {
    asm("mov.b64 {%0, %1}, %2;" : "=f"(lo), "=f"(hi) : "l"(v));
}
__device__ __forceinline__ ull add2(ull a, ull b) {
    ull r; asm("add.rn.f32x2 %0, %1, %2;" : "=l"(r) : "l"(a), "l"(b)); return r;
}
__device__ __forceinline__ ull sub2(ull a, ull b) {
    ull r; asm("sub.rn.f32x2 %0, %1, %2;" : "=l"(r) : "l"(a), "l"(b)); return r;
}
__device__ __forceinline__ ull mul2(ull a, ull b) {
    ull r; asm("mul.rn.f32x2 %0, %1, %2;" : "=l"(r) : "l"(a), "l"(b)); return r;
}
__device__ __forceinline__ ull fma2(ull a, ull b, ull c) {
    ull r; asm("fma.rn.f32x2 %0, %1, %2, %3;" : "=l"(r) : "l"(a), "l"(b), "l"(c)); return r;
}

__global__ __launch_bounds__(NW * 32, 2)
void dyn_dense_kernel(const float* __restrict__ x, const float* __restrict__ ws,
                      const float* __restrict__ qs, const float* __restrict__ bias,
                      float* __restrict__ out)
{
    __shared__ float2 s_invc2[TLEN];               // (1/c, 1/c) duplicated pairs: LDS.64 -> packed
    __shared__ float2 sm_s[NW][32];                // per-chunk partials (float2 = 2 features)
    __shared__ float2 sm_m[NW][32];
    __shared__ float2 sm_q[NW][32];

    const int tid  = threadIdx.x;
    const int warp = tid >> 5;
    const int lane = tid & 31;

    {   // 512 threads, one entry each
        const float ic = 1.0f / (float)(tid + 1);
        s_invc2[tid] = make_float2(ic, ic);
    }

    // grid = B * (FDIM/64); block covers 64 consecutive f, 2 per thread
    const int fblk = blockIdx.x & (FDIM / 64 - 1);   // 16 f-tiles
    const int b    = blockIdx.x >> 4;
    const int f0   = fblk * 64 + lane * 2;

    const size_t colbase2 = ((size_t)b * TLEN * FDIM + (size_t)(warp * CHUNK) * FDIM + f0) >> 1;
    const float2* xp = (const float2*)x + colbase2;

    // ---- Phase 1: per-chunk partials (sum, max, sumsq) over 32 steps ----
    // Max identity 0.0f matches the Keras zero-init of the max state.
    float psx = 0.f, psy = 0.f, pmx = 0.f, pmy = 0.f, pqx = 0.f, pqy = 0.f;
    {
        const float2* p = xp;
        #pragma unroll
        for (int t0 = 0; t0 < CHUNK; t0 += U1) {
            float2 xv[U1];
            #pragma unroll
            for (int u = 0; u < U1; u++)
                xv[u] = __ldg(p + u * F2);          // 16 LDG.64 in flight
            p += U1 * F2;
            #pragma unroll
            for (int u = 0; u < U1; u++) {
                psx += xv[u].x;                 psy += xv[u].y;
                pqx  = fmaf(xv[u].x, xv[u].x, pqx);
                pqy  = fmaf(xv[u].y, xv[u].y, pqy);
                pmx  = fmaxf(pmx, xv[u].x);     pmy  = fmaxf(pmy, xv[u].y);
            }
        }
    }
    sm_s[warp][lane] = make_float2(psx, psy);
    sm_m[warp][lane] = make_float2(pmx, pmy);
    sm_q[warp][lane] = make_float2(pqx, pqy);

    // prefetch first phase-2 batch before the barrier (lines are L2-hot)
    float2 bufA[U2], bufB[U2];
    #pragma unroll
    for (int u = 0; u < U2; u++)
        bufA[u] = __ldg(xp + u * F2);

    __syncthreads();

    // ---- Phase 2: exclusive prefix over earlier chunks ----
    float sx = 0.f, sy = 0.f, mx = 0.f, my = 0.f, ssx = 0.f, ssy = 0.f;
    #pragma unroll
    for (int w = 0; w < NW - 1; w++) {
        if (w < warp) {
            float2 a  = sm_s[w][lane]; sx += a.x;  sy += a.y;
            float2 mm = sm_m[w][lane]; mx = fmaxf(mx, mm.x); my = fmaxf(my, mm.y);
            float2 qv = sm_q[w][lane]; ssx += qv.x; ssy += qv.y;
        }
    }

    // per-aggregation weights (AGGS = sum,max,mean,var,std), packed per thread-pair
    const float2 w0 = __ldg((const float2*)(ws + 0 * FDIM + f0));
    const float2 w1 = __ldg((const float2*)(ws + 1 * FDIM + f0));
    const float2 w2 = __ldg((const float2*)(ws + 2 * FDIM + f0));
    const float2 w3 = __ldg((const float2*)(ws + 3 * FDIM + f0));
    const float2 w4 = __ldg((const float2*)(ws + 4 * FDIM + f0));
    const float2 q0 = __ldg((const float2*)(qs + 0 * FDIM + f0));
    const float2 q1 = __ldg((const float2*)(qs + 1 * FDIM + f0));
    const float2 bb = __ldg((const float2*)(bias + f0));

    const ull W0P = pack2(w0.x, w0.y);
    const ull W1P = pack2(w1.x, w1.y);
    const ull W2P = pack2(w2.x, w2.y);
    const ull W3P = pack2(w3.x, w3.y);
    const ull W4P = pack2(w4.x, w4.y);
    const ull Q0P = pack2(q0.x, q0.y);
    const ull Q1P = pack2(q1.x, q1.y);
    // fold exact eps-correction into bias (z-chain uses w3*(var+eps))
    const ull BZP  = pack2(fmaf(-w3.x, 1e-4f, bb.x), fmaf(-w3.y, 1e-4f, bb.y));
    const ull EPSP = pack2(1e-4f, 1e-4f);
    const ull ONEP = pack2(1.0f, 1.0f);

    const float c0 = (float)(warp * CHUNK);
    ull CPP = pack2(c0 + 1.0f, c0 + 1.0f);         // count, shared by the pair

    const float2* p = xp + U2 * F2;                // bufA already covers steps 0..U2-1
    float2*       o = (float2*)out + colbase2;
    const float2* icp = &s_invc2[warp * CHUNK];

    // one packed scan step: 2 features of one timestep
    auto step = [&](float2 xt, int t) {
        // serial accumulators (scalar; FMNMX has no packed form)
        sx += xt.x;                      sy += xt.y;
        ssx = fmaf(xt.x, xt.x, ssx);     ssy = fmaf(xt.y, xt.y, ssy);
        mx  = fmaxf(mx, xt.x);           my  = fmaxf(my, xt.y);

        const ull SP  = pack2(sx, sy);
        const ull MP  = pack2(mx, my);
        const ull SSP = pack2(ssx, ssy);
        const ull ICP = *(const ull*)&icp[t];      // LDS.64 broadcast, pre-duplicated (ic,ic)

        const ull MEANP = mul2(SP, ICP);
        const ull T1P   = fma2(SSP, ICP, EPSP);    // ss/c + eps
        const ull M2P   = mul2(MEANP, MEANP);
        const ull VEPSP = sub2(T1P, M2P);          // var + eps

        float v0, v1; unpack2(VEPSP, v0, v1);
        const ull SDP = pack2(fast_sqrt(v0), fast_sqrt(v1));

        ull ZP = fma2(Q1P, CPP, Q0P);              // count polynomial
        ZP = fma2(ZP, CPP, BZP);                   // BZP holds eps fix
        ZP = fma2(W0P, SP,    ZP);
        ZP = fma2(W1P, MP,    ZP);
        ZP = fma2(W2P, MEANP, ZP);
        ZP = fma2(W3P, VEPSP, ZP);
        ZP = fma2(W4P, SDP,   ZP);
        CPP = add2(CPP, ONEP);

        float z0, z1; unpack2(ZP, z0, z1);
        float2 r; r.x = fast_tanh(z0); r.y = fast_tanh(z1);
        o[t * F2] = r;                             // STG.64
    };

    // double-buffered scan; reloads are L2-hot (block's set resident in L2)
    #pragma unroll
    for (int t0 = 0; t0 < CHUNK; t0 += 2 * U2) {
        #pragma unroll
        for (int u = 0; u < U2; u++)
            bufB[u] = __ldg(p + u * F2);
        p += U2 * F2;
        #pragma unroll
        for (int u = 0; u < U2; u++)
            step(bufA[u], t0 + u);

        if (t0 + 2 * U2 < CHUNK) {
            #pragma unroll
            for (int u = 0; u < U2; u++)
                bufA[u] = __ldg(p + u * F2);
            p += U2 * F2;
        }
        #pragma unroll
        for (int u = 0; u < U2; u++)
            step(bufB[u], t0 + U2 + u);
    }
}

extern "C" void kernel_launch(void* const* d_in, const int* in_sizes, int n_in,
                              void* d_out, int out_size)
{
    const float* x    = (const float*)d_in[0];
    const float* ws   = (const float*)d_in[1];
    const float* qs   = (const float*)d_in[2];
    const float* bias = (const float*)d_in[3];
    float* out = (float*)d_out;

    const int grid = 32 * (FDIM / 64);   // B * 16 f-tiles = 512 blocks
    dyn_dense_kernel<<<grid, NW * 32>>>(x, ws, qs, bias, out);
}